// round 13
// baseline (speedup 1.0000x reference)
#include <cuda_runtime.h>
#include <cuda_bf16.h>

#define T_MAX 11

// Kernel-A -> Kernel-B handoff (graph edge orders the kernels).
__device__ float g_w[1024];
__device__ int   g_off[1024];
__device__ int   g_cnt[1024];

// ---------------------------------------------------------------------------
// Kernel A: ONE block, 1024 threads. Does everything small:
//   - warp w computes dots for rows w, w+32, ... (full MLP, one SM)
//   - per-segment softmax (intra-block, no rendezvous)
//   - writes g_w / g_off / g_cnt and the probs output rows
// ---------------------------------------------------------------------------
__global__ void __launch_bounds__(1024)
k_prep(const float* __restrict__ hist,
       const float* __restrict__ Wv,
       const float* __restrict__ bv,
       const int*   __restrict__ slice_mask,
       float* __restrict__ probs_out,
       int rows, int hidden, int S)
{
    __shared__ float s_e[256];
    __shared__ int   s_mask[64], s_off[64];

    const int tid  = threadIdx.x;
    const int lane = tid & 31;
    const int warp = tid >> 5;

    const int nv4 = hidden >> 2;                    // 192 @ hidden=768
    const float4* wv = (const float4*)Wv;

    // ---- row dots: warp per row, strided by 32 warps ----
    for (int r = warp; r < rows; r += 32) {
        const float4* hr = (const float4*)(hist + (size_t)r * hidden);
        float acc = 0.f;
        #pragma unroll 2
        for (int c = lane; c < nv4; c += 32) {      // 6 independent rounds
            float4 h = __ldg(hr + c);
            float4 w = __ldg(wv + c);
            acc = fmaf(h.x, w.x, acc);
            acc = fmaf(h.y, w.y, acc);
            acc = fmaf(h.z, w.z, acc);
            acc = fmaf(h.w, w.w, acc);
        }
        #pragma unroll
        for (int o = 16; o; o >>= 1)
            acc += __shfl_down_sync(0xffffffffu, acc, o);
        if (lane == 0) s_e[r] = __expf(acc + __ldg(bv));
    }

    if (tid < S) s_mask[tid] = __ldg(slice_mask + tid);
    __syncthreads();                                // s_e + s_mask ready

    if (tid == 0) {
        int o = 0;
        for (int t = 0; t < S; t++) { s_off[t] = o; o += s_mask[t]; }
    }
    __syncthreads();

    // ---- per-segment softmax + outputs ----
    if (tid < S) {
        const int off = s_off[tid], cnt = s_mask[tid];
        g_off[tid] = off;
        g_cnt[tid] = cnt;
        float sum = 0.f;
        for (int j = 0; j < cnt; j++) sum += s_e[off + j];
        const float inv  = 1.f / sum;
        const int   padl = T_MAX - cnt;
        for (int j = 0; j < cnt; j++)
            g_w[off + j] = s_e[off + j] * inv;
        // probs row (d_out poisoned: write all T_MAX slots)
        for (int t = 0; t < T_MAX; t++)
            probs_out[tid * T_MAX + t] =
                (t >= padl) ? s_e[off + t - padl] * inv : 0.f;
    }
}

// ---------------------------------------------------------------------------
// Kernel B: proven streaming segment-sum (R6 shape: 19.9us, 69% DRAM).
//   blockIdx.y = segment s.
//   blockIdx.x <  GX-1 : 256 float4 chunk of new_bert
//   blockIdx.x == GX-1 : new_mtl row s
// Prologue = single round of L2-hot scalar loads (g_off/g_cnt), weights
// read as L2-hot scalars inside the j-loop. No barriers, no math.
// ---------------------------------------------------------------------------
__global__ void __launch_bounds__(256)
k_segsum(const float* __restrict__ bert,
         const float* __restrict__ mtl,
         float* __restrict__ out_bert,
         float* __restrict__ out_mtl,
         int n4_bert, int n4_mtl)
{
    const int s   = blockIdx.y;
    const int off = g_off[s];
    const int cnt = g_cnt[s];

    if ((int)blockIdx.x < (int)gridDim.x - 1) {
        int e = blockIdx.x * blockDim.x + threadIdx.x;
        if (e >= n4_bert) return;
        const float4* base = (const float4*)bert + (size_t)off * n4_bert + e;
        float4 acc = make_float4(0.f, 0.f, 0.f, 0.f);
        for (int j = 0; j < cnt; j++) {
            float  w = g_w[off + j];
            float4 v = __ldg(base + (size_t)j * n4_bert);
            acc.x = fmaf(w, v.x, acc.x);
            acc.y = fmaf(w, v.y, acc.y);
            acc.z = fmaf(w, v.z, acc.z);
            acc.w = fmaf(w, v.w, acc.w);
        }
        ((float4*)out_bert)[(size_t)s * n4_bert + e] = acc;
    } else {
        int e = threadIdx.x;
        if (e >= n4_mtl) return;
        const float4* base = (const float4*)mtl + (size_t)off * n4_mtl + e;
        float4 acc = make_float4(0.f, 0.f, 0.f, 0.f);
        for (int j = 0; j < cnt; j++) {
            float  w = g_w[off + j];
            float4 v = __ldg(base + (size_t)j * n4_mtl);
            acc.x = fmaf(w, v.x, acc.x);
            acc.y = fmaf(w, v.y, acc.y);
            acc.z = fmaf(w, v.z, acc.z);
            acc.w = fmaf(w, v.w, acc.w);
        }
        ((float4*)out_mtl)[(size_t)s * n4_mtl + e] = acc;
    }
}

// ---------------------------------------------------------------------------
// Launch. Inputs (metadata order):
//   0: bert_representation (rows, seq, hidden) f32
//   1: history_attention_input (rows, hidden)  f32
//   2: mtl_input (rows, hidden)                f32
//   3: W (1, hidden) f32     4: b (1,) f32
//   5: slice_mask (rows,) i32   6: slice_num i32 (S derived from out_size)
// Output: [new_bert (S,seq,hidden) | new_mtl (S,hidden) | probs (S,T_MAX)] f32
// ---------------------------------------------------------------------------
extern "C" void kernel_launch(void* const* d_in, const int* in_sizes, int n_in,
                              void* d_out, int out_size)
{
    const float* bert = (const float*)d_in[0];
    const float* hist = (const float*)d_in[1];
    const float* mtl  = (const float*)d_in[2];
    const float* Wv   = (const float*)d_in[3];
    const float* bv   = (const float*)d_in[4];
    const int*   sm   = (const int*)d_in[5];

    const int hidden = in_sizes[3];                   // 768
    const int rows   = in_sizes[1] / hidden;          // 64
    const int seq    = in_sizes[0] / (rows * hidden); // 512
    const int S      = out_size / (seq * hidden + hidden + T_MAX); // 16

    float* out_bert  = (float*)d_out;
    float* out_mtl   = out_bert + (size_t)S * seq * hidden;
    float* out_probs = out_mtl  + (size_t)S * hidden;

    const int n4_bert = seq * hidden / 4;   // 98304
    const int n4_mtl  = hidden / 4;         // 192

    k_prep<<<1, 1024>>>(hist, Wv, bv, sm, out_probs, rows, hidden, S);

    dim3 grid((n4_bert + 255) / 256 + 1, S);  // (385, 16)
    k_segsum<<<grid, 256>>>(bert, mtl, out_bert, out_mtl, n4_bert, n4_mtl);
}